// round 1
// baseline (speedup 1.0000x reference)
#include <cuda_runtime.h>
#include <math.h>

#define BB 4
#define NN 256
#define EDGEF 256
#define MSG 128
#define CLS 600
#define ADJ_ELEMS (BB*NN*NN)

// ---- scratch (device globals; zero-initialized at module load) ----
__device__ float g_nf[BB*NN*MSG];            // node features resized        [B,N,128]
__device__ float g_nfm[BB*NN*MSG];           // nf @ W_msg[0:128] (no bias)  [B,N,128]
__device__ float g_mraw[(size_t)BB*NN*NN*MSG]; // relu message, round-invariant [B,N,N,128] (128MB)
__device__ float g_gate[2][BB*NN*NN];        // sigmoid(pred_adj) ping-pong  [B,N,N]
__device__ float g_msum[BB*NN*MSG];          // final message sum            [B,N,128]

__device__ __forceinline__ float sigmoidf_(float x) { return 1.f / (1.f + __expf(-x)); }

// Accumulate one K-chunk of 32: acc[8][4] += A(64xK tile) * Bs(32x128)
__device__ __forceinline__ void mm_chunk(const float* __restrict__ Apanel, int lda,
                                         const float* __restrict__ Bs,
                                         int row0, int lane, float acc[8][4]) {
#pragma unroll
    for (int kk = 0; kk < 32; kk += 4) {
        float4 b0 = ((const float4*)(Bs + (kk + 0) * MSG))[lane];
        float4 b1 = ((const float4*)(Bs + (kk + 1) * MSG))[lane];
        float4 b2 = ((const float4*)(Bs + (kk + 2) * MSG))[lane];
        float4 b3 = ((const float4*)(Bs + (kk + 3) * MSG))[lane];
#pragma unroll
        for (int r = 0; r < 8; r++) {
            float4 av = *(const float4*)(Apanel + (row0 + r) * lda + kk);
            acc[r][0] += av.x * b0.x; acc[r][0] += av.y * b1.x; acc[r][0] += av.z * b2.x; acc[r][0] += av.w * b3.x;
            acc[r][1] += av.x * b0.y; acc[r][1] += av.y * b1.y; acc[r][1] += av.z * b2.y; acc[r][1] += av.w * b3.y;
            acc[r][2] += av.x * b0.z; acc[r][2] += av.y * b1.z; acc[r][2] += av.z * b2.z; acc[r][2] += av.w * b3.z;
            acc[r][3] += av.x * b0.w; acc[r][3] += av.y * b1.w; acc[r][3] += av.z * b2.w; acc[r][3] += av.w * b3.w;
        }
    }
}

// ---- nf = node @ W_nr + b_nr ; nfm = nf @ W_msg[0:128,:] (sender half of message GEMM) ----
__global__ __launch_bounds__(128) void k_nf(const float* __restrict__ node,
                                            const float* __restrict__ W_nr,
                                            const float* __restrict__ b_nr,
                                            const float* __restrict__ W_msg) {
    int i = blockIdx.x, b = blockIdx.y, t = threadIdx.x;
    __shared__ float xs[EDGEF];
    __shared__ float nfsh[MSG];
    const float* xr = node + ((size_t)b * NN + i) * EDGEF;
    xs[t] = xr[t];
    xs[t + 128] = xr[t + 128];
    __syncthreads();
    float acc = b_nr[t];
#pragma unroll 8
    for (int k = 0; k < EDGEF; k++) acc += xs[k] * W_nr[k * MSG + t];
    g_nf[((size_t)b * NN + i) * MSG + t] = acc;
    nfsh[t] = acc;
    __syncthreads();
    float am = 0.f;
#pragma unroll 8
    for (int k = 0; k < MSG; k++) am += nfsh[k] * W_msg[k * MSG + t];
    g_nfm[((size_t)b * NN + i) * MSG + t] = am;
}

// ---- fused: ef tile (smem only) -> m_raw (global) + round-0 link gate (global) ----
// block = (w_tile of 64, i, b); 256 threads, 8x4 micro-tile each.
__global__ __launch_bounds__(256) void k_ef(const float* __restrict__ edge,
                                            const float* __restrict__ W_er, const float* __restrict__ b_er,
                                            const float* __restrict__ W_msg, const float* __restrict__ b_msg,
                                            const float* __restrict__ W_l1, const float* __restrict__ b_l1,
                                            const float* __restrict__ W_l2, const float* __restrict__ b_l2,
                                            const int* __restrict__ hn, const int* __restrict__ on) {
    int b = blockIdx.z, i = blockIdx.y, w0 = blockIdx.x * 64;
    int valid = hn[b] + on[b];
    if (i >= valid || w0 >= valid) return;
    int wn = min(64, valid - w0);

    __shared__ float efs[64 * MSG];   // ef tile (also aliased as A-staging during GEMM1)
    __shared__ float Bs[32 * MSG];    // B tile
    float* As = efs;                  // alias: GEMM1 A staging (first 2048 floats), efs written after

    int tid = threadIdx.x;
    int rg = tid >> 5, lane = tid & 31;
    int row0 = rg * 8;

    float acc[8][4];
#pragma unroll
    for (int r = 0; r < 8; r++) { acc[r][0] = acc[r][1] = acc[r][2] = acc[r][3] = 0.f; }

    const float* Abase = edge + (((size_t)b * NN + i) * NN + w0) * EDGEF;

    // GEMM1: ef = edge(64x256) @ W_er(256x128)
    for (int kc = 0; kc < EDGEF; kc += 32) {
        for (int t = tid; t < 512; t += 256) {
            int r = t >> 3, c4 = t & 7;
            ((float4*)As)[t] = *(const float4*)(Abase + (size_t)r * EDGEF + kc + c4 * 4);
        }
        for (int t = tid; t < 1024; t += 256)
            ((float4*)Bs)[t] = ((const float4*)(W_er + kc * MSG))[t];
        __syncthreads();
        mm_chunk(As, 32, Bs, row0, lane, acc);
        __syncthreads();
    }
    {   // efs = acc + b_er (write after all As reads done — alias safe)
        float4 be = ((const float4*)b_er)[lane];
#pragma unroll
        for (int r = 0; r < 8; r++) {
            float4 v;
            v.x = acc[r][0] + be.x; v.y = acc[r][1] + be.y; v.z = acc[r][2] + be.z; v.w = acc[r][3] + be.w;
            ((float4*)(efs + (row0 + r) * MSG))[lane] = v;
        }
    }
    __syncthreads();

    // GEMM2: m_raw = relu(nfm[w] + efs @ W_msg[128:256,:] + b_msg)
#pragma unroll
    for (int r = 0; r < 8; r++) { acc[r][0] = acc[r][1] = acc[r][2] = acc[r][3] = 0.f; }
    for (int kc = 0; kc < MSG; kc += 32) {
        for (int t = tid; t < 1024; t += 256)
            ((float4*)Bs)[t] = ((const float4*)(W_msg + (MSG + kc) * MSG))[t];
        __syncthreads();
        mm_chunk(efs + kc, MSG, Bs, row0, lane, acc);
        __syncthreads();
    }
    {
        float4 bm = ((const float4*)b_msg)[lane];
#pragma unroll
        for (int r = 0; r < 8; r++) {
            int row = row0 + r;
            if (row < wn) {
                float4 nm = ((const float4*)(g_nfm + ((size_t)b * NN + w0 + row) * MSG))[lane];
                float4 v;
                v.x = fmaxf(acc[r][0] + nm.x + bm.x, 0.f);
                v.y = fmaxf(acc[r][1] + nm.y + bm.y, 0.f);
                v.z = fmaxf(acc[r][2] + nm.z + bm.z, 0.f);
                v.w = fmaxf(acc[r][3] + nm.w + bm.w, 0.f);
                ((float4*)(g_mraw + (((size_t)b * NN + i) * NN + w0 + row) * MSG))[lane] = v;
            }
        }
    }

    // GEMM3: round-0 link on e_state_0 = ef:  s = relu(ef@W_l1+b_l1)@W_l2 + b_l2
#pragma unroll
    for (int r = 0; r < 8; r++) { acc[r][0] = acc[r][1] = acc[r][2] = acc[r][3] = 0.f; }
    for (int kc = 0; kc < MSG; kc += 32) {
        for (int t = tid; t < 1024; t += 256)
            ((float4*)Bs)[t] = ((const float4*)(W_l1 + kc * MSG))[t];
        __syncthreads();
        mm_chunk(efs + kc, MSG, Bs, row0, lane, acc);
        __syncthreads();
    }
    {
        float4 bl = ((const float4*)b_l1)[lane];
        float4 w2 = ((const float4*)W_l2)[lane];
        float bL2 = b_l2[0];
#pragma unroll
        for (int r = 0; r < 8; r++) {
            float h0 = fmaxf(acc[r][0] + bl.x, 0.f);
            float h1 = fmaxf(acc[r][1] + bl.y, 0.f);
            float h2 = fmaxf(acc[r][2] + bl.z, 0.f);
            float h3 = fmaxf(acc[r][3] + bl.w, 0.f);
            float p = h0 * w2.x + h1 * w2.y + h2 * w2.z + h3 * w2.w;
#pragma unroll
            for (int off = 16; off > 0; off >>= 1) p += __shfl_down_sync(0xffffffffu, p, off);
            if (lane == 0) {
                int row = row0 + r;
                if (row < wn)
                    g_gate[0][((size_t)b * NN + i) * NN + w0 + row] = sigmoidf_(p + bL2);
            }
        }
    }
}

// ---- link rounds 1/2: x = gate_src[w][i] * m_raw[w][i]; s = relu(x@W_l1+b)@W_l2+b2 ----
__global__ __launch_bounds__(256) void k_link(const float* __restrict__ W_l1, const float* __restrict__ b_l1,
                                              const float* __restrict__ W_l2, const float* __restrict__ b_l2,
                                              const int* __restrict__ hn, const int* __restrict__ on,
                                              int src, int dst, float* __restrict__ adj_out) {
    int b = blockIdx.z, i = blockIdx.y, w0 = blockIdx.x * 64;
    int valid = hn[b] + on[b];
    if (i >= valid || w0 >= valid) return;
    int wn = min(64, valid - w0);

    __shared__ float xs[64 * MSG];
    __shared__ float Bs[32 * MSG];

    int tid = threadIdx.x;
    int rg = tid >> 5, lane = tid & 31;
    int row0 = rg * 8;

    // xs[r] = gate_src[b][w0+r][i] * m_raw[b][w0+r][i][:]   (transposed read; unwritten region is 0)
    for (int t = tid; t < 64 * 32; t += 256) {
        int r = t >> 5, c4 = t & 31;
        size_t eidx = ((size_t)b * NN + (w0 + r)) * NN + i;
        float g = g_gate[src][eidx];
        float4 mv = ((const float4*)(g_mraw + eidx * MSG))[c4];
        float4 v; v.x = g * mv.x; v.y = g * mv.y; v.z = g * mv.z; v.w = g * mv.w;
        ((float4*)(xs + r * MSG))[c4] = v;
    }

    float acc[8][4];
#pragma unroll
    for (int r = 0; r < 8; r++) { acc[r][0] = acc[r][1] = acc[r][2] = acc[r][3] = 0.f; }
    for (int kc = 0; kc < MSG; kc += 32) {
        for (int t = tid; t < 1024; t += 256)
            ((float4*)Bs)[t] = ((const float4*)(W_l1 + kc * MSG))[t];
        __syncthreads();
        mm_chunk(xs + kc, MSG, Bs, row0, lane, acc);
        __syncthreads();
    }
    {
        float4 bl = ((const float4*)b_l1)[lane];
        float4 w2 = ((const float4*)W_l2)[lane];
        float bL2 = b_l2[0];
#pragma unroll
        for (int r = 0; r < 8; r++) {
            float h0 = fmaxf(acc[r][0] + bl.x, 0.f);
            float h1 = fmaxf(acc[r][1] + bl.y, 0.f);
            float h2 = fmaxf(acc[r][2] + bl.z, 0.f);
            float h3 = fmaxf(acc[r][3] + bl.w, 0.f);
            float p = h0 * w2.x + h1 * w2.y + h2 * w2.z + h3 * w2.w;
#pragma unroll
            for (int off = 16; off > 0; off >>= 1) p += __shfl_down_sync(0xffffffffu, p, off);
            if (lane == 0) {
                int row = row0 + r;
                if (row < wn) {
                    size_t oidx = ((size_t)b * NN + i) * NN + w0 + row;
                    float s = p + bL2;
                    g_gate[dst][oidx] = sigmoidf_(s);
                    if (adj_out) adj_out[oidx] = s;   // final-round pred_adj (pair_mask==1 here)
                }
            }
        }
    }
}

// ---- m_sum[i] = sum_{w<valid} gate2[i][w] * m_raw[i][w][:] ----
__global__ __launch_bounds__(128) void k_msum(const int* __restrict__ hn, const int* __restrict__ on) {
    int i = blockIdx.x, b = blockIdx.y, t = threadIdx.x;
    int valid = hn[b] + on[b];
    if (i >= valid) return;
    const float* gr = g_gate[0] + ((size_t)b * NN + i) * NN;       // gate2 lives in slot 0
    const float* mr = g_mraw + (((size_t)b * NN + i) * NN) * MSG;
    float acc = 0.f;
    for (int w = 0; w < valid; w++) acc += gr[w] * mr[(size_t)w * MSG + t];
    g_msum[((size_t)b * NN + i) * MSG + t] = acc;
}

// ---- GRU cell + readout (valid nodes only) ----
__global__ __launch_bounds__(128) void k_gru(const float* __restrict__ W_ih, const float* __restrict__ b_ih,
                                             const float* __restrict__ W_hh, const float* __restrict__ b_hh,
                                             const float* __restrict__ W_ro, const float* __restrict__ b_ro,
                                             const int* __restrict__ hn, const int* __restrict__ on,
                                             float* __restrict__ out_labels) {
    int i = blockIdx.x, b = blockIdx.y, t = threadIdx.x;
    int valid = hn[b] + on[b];
    if (i >= valid) return;
    __shared__ float xsm[MSG], hsm[MSG], hnew[MSG];
    xsm[t] = g_msum[((size_t)b * NN + i) * MSG + t];
    hsm[t] = g_nf[((size_t)b * NN + i) * MSG + t];
    __syncthreads();
    float ir = b_ih[t], iz = b_ih[128 + t], inn = b_ih[256 + t];
    float hr = b_hh[t], hz = b_hh[128 + t], hnn = b_hh[256 + t];
#pragma unroll 4
    for (int k = 0; k < MSG; k++) {
        float x = xsm[k], h = hsm[k];
        const float* wi = W_ih + k * 384;
        const float* wh = W_hh + k * 384;
        ir += x * wi[t]; iz += x * wi[128 + t]; inn += x * wi[256 + t];
        hr += h * wh[t]; hz += h * wh[128 + t]; hnn += h * wh[256 + t];
    }
    float r = sigmoidf_(ir + hr);
    float z = sigmoidf_(iz + hz);
    float n = tanhf(inn + r * hnn);
    hnew[t] = (1.f - z) * n + z * hsm[t];
    __syncthreads();
    float* orow = out_labels + ((size_t)b * NN + i) * CLS;
    for (int c = t; c < CLS; c += 128) {
        float acc = b_ro[c];
#pragma unroll 4
        for (int k = 0; k < MSG; k++) acc += hnew[k] * W_ro[k * CLS + c];
        orow[c] = acc;
    }
}

extern "C" void kernel_launch(void* const* d_in, const int* in_sizes, int n_in,
                              void* d_out, int out_size) {
    const float* edge  = (const float*)d_in[0];
    const float* node  = (const float*)d_in[1];
    // d_in[2] adj_mat, d_in[3] node_labels: unused (zeros)
    const int*   hn    = (const int*)d_in[4];
    const int*   on    = (const int*)d_in[5];
    const float* W_er  = (const float*)d_in[6];   const float* b_er  = (const float*)d_in[7];
    const float* W_nr  = (const float*)d_in[8];   const float* b_nr  = (const float*)d_in[9];
    const float* W_l1  = (const float*)d_in[10];  const float* b_l1  = (const float*)d_in[11];
    const float* W_l2  = (const float*)d_in[12];  const float* b_l2  = (const float*)d_in[13];
    const float* W_msg = (const float*)d_in[14];  const float* b_msg = (const float*)d_in[15];
    const float* W_ih  = (const float*)d_in[16];  const float* b_ih  = (const float*)d_in[17];
    const float* W_hh  = (const float*)d_in[18];  const float* b_hh  = (const float*)d_in[19];
    const float* W_ro  = (const float*)d_in[20];  const float* b_ro  = (const float*)d_in[21];
    float* out = (float*)d_out;

    cudaMemsetAsync(out, 0, (size_t)out_size * sizeof(float), 0);

    k_nf<<<dim3(NN, BB), 128>>>(node, W_nr, b_nr, W_msg);
    k_ef<<<dim3(4, NN, BB), 256>>>(edge, W_er, b_er, W_msg, b_msg, W_l1, b_l1, W_l2, b_l2, hn, on);
    k_link<<<dim3(4, NN, BB), 256>>>(W_l1, b_l1, W_l2, b_l2, hn, on, 0, 1, nullptr);       // round 1
    k_link<<<dim3(4, NN, BB), 256>>>(W_l1, b_l1, W_l2, b_l2, hn, on, 1, 0, out);           // round 2 -> pred_adj
    k_msum<<<dim3(NN, BB), 128>>>(hn, on);
    k_gru<<<dim3(NN, BB), 128>>>(W_ih, b_ih, W_hh, b_hh, W_ro, b_ro, hn, on, out + ADJ_ELEMS);
}